// round 2
// baseline (speedup 1.0000x reference)
#include <cuda_runtime.h>
#include <cfloat>
#include <math.h>

// Problem constants
#define NN 16384
#define MM 32768
#define KK 8
#define CC 256
#define GG 4                  // M-splits for KNN parallelism
#define MSEG (MM / GG)        // 8192
#define TILE 1024             // cond candidates per shared tile

// Scratch (device globals; no allocations allowed)
__device__ float g_pd[GG * NN * KK];   // partial top-8 squared dists
__device__ int   g_pi[GG * NN * KK];   // partial top-8 indices
__device__ float g_favg[NN * CC];      // weighted-average features
__device__ float g_tf[CC];             // timestep feature vector

// ---------------------------------------------------------------------------
// Kernel 1: timestep embedding -> 2-layer MLP -> g_tf[256]
// Internals in fp64 so each f32 result is correctly rounded (reference host
// uses glibc sinf/expf, which are near-correctly-rounded).
// ---------------------------------------------------------------------------
__global__ void k_tfeats(const float* __restrict__ t,
                         const float* __restrict__ Wt1, const float* __restrict__ bt1,
                         const float* __restrict__ Wt2, const float* __restrict__ bt2) {
    __shared__ float emb[96];
    __shared__ float h1[96];
    int tid = threadIdx.x;
    float tv = t[0];
    if (tid < 48) {
        // c = f32(-log(10000)/47) exactly as JAX converts the python f64 scalar
        const double c64 = -9.210340371976184 / 47.0;
        float cf = (float)c64;
        float arg = __fmul_rn((float)tid, cf);          // f32 multiply like ref
        float f = (float)exp((double)arg);              // correctly-rounded expf
        float e = __fmul_rn(tv, f);                     // f32 multiply like ref
        emb[tid]      = (float)sin((double)e);
        emb[tid + 48] = (float)cos((double)e);
    }
    __syncthreads();
    if (tid < 96) {
        float acc = 0.0f;
        #pragma unroll 8
        for (int j = 0; j < 96; ++j) acc += emb[j] * Wt1[tid * 96 + j];
        acc += bt1[tid];
        h1[tid] = (acc >= 0.0f) ? acc : 0.1f * acc;   // leaky_relu(0.1)
    }
    __syncthreads();
    if (tid < 256) {
        float acc = 0.0f;
        #pragma unroll 8
        for (int j = 0; j < 96; ++j) acc += h1[j] * Wt2[tid * 96 + j];
        acc += bt2[tid];
        g_tf[tid] = acc;
    }
}

// ---------------------------------------------------------------------------
// Kernel 2: brute-force KNN, partial top-8 over an M-segment per blockIdx.y
// One thread = one node. Candidates streamed through shared memory.
//
// Distance scheme must replicate XLA:CPU bit-for-bit (exact real ties at the
// k=8 boundary are resolved by rounding noise). XLA:CPU compiles the lax.map
// body with AllowFPOpFusion::Fast -> the 4-elem reduce becomes an fmla chain:
//   d = fma(dz,dz, fma(dy,dy, fma(dx,dx, fma(b,b,0)))) , b==0
//     = fma(dz,dz, fma(dy,dy, rn(dx*dx)))
// Strict '<' insertion scanning ascending indices reproduces top_k's
// lower-index-wins tie break.
// ---------------------------------------------------------------------------
__global__ void __launch_bounds__(128) k_knn(const int* __restrict__ node_c,
                                             const int* __restrict__ cond_c) {
    __shared__ float4 sc[TILE];
    int n = blockIdx.x * 128 + threadIdx.x;

    const int4 nc = ((const int4*)node_c)[n];
    // node transform: (c + 16/2) * 0.05   (elementwise add then mul, f32)
    float nx = __fmul_rn(__fadd_rn((float)nc.y, 8.0f), 0.05f);
    float ny = __fmul_rn(__fadd_rn((float)nc.z, 8.0f), 0.05f);
    float nz = __fmul_rn(__fadd_rn((float)nc.w, 8.0f), 0.05f);

    float bd[KK];
    int   bi[KK];
    #pragma unroll
    for (int s = 0; s < KK; ++s) { bd[s] = FLT_MAX; bi[s] = 0x7fffffff; }

    const int m0 = blockIdx.y * MSEG;

    for (int t0 = 0; t0 < MSEG; t0 += TILE) {
        // cooperative coalesced load + transform: (c + 1/2) * 0.01
        for (int j = threadIdx.x; j < TILE; j += 128) {
            int4 cc = ((const int4*)cond_c)[m0 + t0 + j];
            sc[j] = make_float4(__fmul_rn(__fadd_rn((float)cc.y, 0.5f), 0.01f),
                                __fmul_rn(__fadd_rn((float)cc.z, 0.5f), 0.01f),
                                __fmul_rn(__fadd_rn((float)cc.w, 0.5f), 0.01f),
                                0.0f);
        }
        __syncthreads();

        #pragma unroll 4
        for (int j = 0; j < TILE; ++j) {
            float4 p = sc[j];
            float dx = __fadd_rn(nx, -p.x);
            float dy = __fadd_rn(ny, -p.y);
            float dz = __fadd_rn(nz, -p.z);
            // XLA fmla reduce chain (see header comment)
            float d = __fmaf_rn(dz, dz, __fmaf_rn(dy, dy, __fmul_rn(dx, dx)));
            if (d < bd[KK - 1]) {
                bd[KK - 1] = d;
                bi[KK - 1] = m0 + t0 + j;
                #pragma unroll
                for (int s = KK - 1; s > 0; --s) {
                    if (bd[s] < bd[s - 1]) {
                        float td = bd[s]; bd[s] = bd[s - 1]; bd[s - 1] = td;
                        int   ti = bi[s]; bi[s] = bi[s - 1]; bi[s - 1] = ti;
                    }
                }
            }
        }
        __syncthreads();
    }

    int base = (blockIdx.y * NN + n) * KK;
    #pragma unroll
    for (int s = 0; s < KK; ++s) {
        g_pd[base + s] = bd[s];
        g_pi[base + s] = bi[s];
    }
}

// ---------------------------------------------------------------------------
// Kernel 3: per-node merge of 4x8 partials -> global top-8, inverse-distance
// weights, weighted feature gather -> g_favg. One warp per node.
// ---------------------------------------------------------------------------
__global__ void __launch_bounds__(256) k_merge(const float* __restrict__ cond_feats) {
    int warp = threadIdx.x >> 5;
    int lane = threadIdx.x & 31;
    int n = blockIdx.x * 8 + warp;

    // lane l holds partial (g = l>>3, s = l&7)
    int src = (((lane >> 3) * NN + n) * KK) + (lane & 7);
    float d  = g_pd[src];
    int   id = g_pi[src];

    float wd[KK];
    int   wi[KK];
    #pragma unroll
    for (int k = 0; k < KK; ++k) {
        float bdv = d; int biv = id;
        #pragma unroll
        for (int off = 16; off > 0; off >>= 1) {
            float od = __shfl_xor_sync(0xffffffffu, bdv, off);
            int   oi = __shfl_xor_sync(0xffffffffu, biv, off);
            if (od < bdv || (od == bdv && oi < biv)) { bdv = od; biv = oi; }
        }
        wd[k] = bdv; wi[k] = biv;
        if (id == biv) d = FLT_MAX;   // invalidate selected (indices unique)
    }

    // weights: w_k = 1/max(sqrt(d), 1e-6), normalized by division (match ref)
    float w[KK];
    float wsum = 0.0f;
    #pragma unroll
    for (int k = 0; k < KK; ++k) {
        float dist = fmaxf(sqrtf(wd[k]), 1e-6f);
        w[k] = 1.0f / dist;
        wsum += w[k];
    }
    #pragma unroll
    for (int k = 0; k < KK; ++k) w[k] = w[k] / wsum;

    const float* rp[KK];
    #pragma unroll
    for (int k = 0; k < KK; ++k) rp[k] = cond_feats + (size_t)wi[k] * CC;

    float* outp = g_favg + (size_t)n * CC;
    #pragma unroll
    for (int j = 0; j < 8; ++j) {
        int c = lane + j * 32;
        float acc = 0.0f;
        #pragma unroll
        for (int k = 0; k < KK; ++k) acc = fmaf(w[k], rp[k][c], acc);
        outp[c] = acc;
    }
}

// ---------------------------------------------------------------------------
// Kernel 4: fused 3-layer MLP  out = (leaky((favg Wp^T + bp) Wl1^T + bl1) Wl2^T + bl2) + tf
// 32 rows/block, 256 threads; thread = (ry row-group of 4) x (cx, 8 columns).
// Weights streamed through shared in 256x32 tiles.
// ---------------------------------------------------------------------------
__global__ void __launch_bounds__(256) k_mlp(const float* __restrict__ Wp, const float* __restrict__ bp,
                                             const float* __restrict__ W1, const float* __restrict__ b1,
                                             const float* __restrict__ W2, const float* __restrict__ b2,
                                             float* __restrict__ out) {
    extern __shared__ float sm[];
    float* Xs = sm;                 // 32 x 256
    float* Ws = sm + 32 * 256;      // 256 x 33 (padded)

    int tid = threadIdx.x;
    int cx = tid & 31;
    int ry = tid >> 5;              // warp id 0..7
    int row0 = blockIdx.x * 32;

    // load X rows (coalesced)
    for (int e = tid; e < 32 * 256; e += 256) {
        Xs[e] = g_favg[(size_t)row0 * 256 + e];
    }
    __syncthreads();

    const float* Wl[3] = {Wp, W1, W2};
    const float* bl[3] = {bp, b1, b2};

    for (int layer = 0; layer < 3; ++layer) {
        const float* W = Wl[layer];
        float acc[4][8];
        #pragma unroll
        for (int i = 0; i < 4; ++i)
            #pragma unroll
            for (int k = 0; k < 8; ++k) acc[i][k] = 0.0f;

        for (int ct = 0; ct < 256; ct += 32) {
            // warp ry loads W rows [ry*32, ry*32+32), cols [ct, ct+32)
            #pragma unroll 4
            for (int dd = 0; dd < 32; ++dd) {
                int dr = ry * 32 + dd;
                Ws[dr * 33 + cx] = W[dr * 256 + ct + cx];
            }
            __syncthreads();

            #pragma unroll
            for (int c = 0; c < 32; ++c) {
                float wv[8];
                #pragma unroll
                for (int k = 0; k < 8; ++k) wv[k] = Ws[(cx + 32 * k) * 33 + c];
                float xv[4];
                #pragma unroll
                for (int i = 0; i < 4; ++i) xv[i] = Xs[(ry * 4 + i) * 256 + ct + c];
                #pragma unroll
                for (int i = 0; i < 4; ++i)
                    #pragma unroll
                    for (int k = 0; k < 8; ++k)
                        acc[i][k] = fmaf(xv[i], wv[k], acc[i][k]);
            }
            __syncthreads();
        }

        // epilogue
        float bias[8];
        #pragma unroll
        for (int k = 0; k < 8; ++k) bias[k] = bl[layer][cx + 32 * k];

        if (layer < 2) {
            #pragma unroll
            for (int i = 0; i < 4; ++i)
                #pragma unroll
                for (int k = 0; k < 8; ++k) {
                    float v = acc[i][k] + bias[k];
                    if (layer == 1) v = (v >= 0.0f) ? v : 0.1f * v;  // leaky after l1
                    Xs[(ry * 4 + i) * 256 + cx + 32 * k] = v;
                }
            __syncthreads();
        } else {
            float tf[8];
            #pragma unroll
            for (int k = 0; k < 8; ++k) tf[k] = g_tf[cx + 32 * k];
            #pragma unroll
            for (int i = 0; i < 4; ++i) {
                int r = row0 + ry * 4 + i;
                #pragma unroll
                for (int k = 0; k < 8; ++k)
                    out[(size_t)r * 256 + cx + 32 * k] = acc[i][k] + bias[k] + tf[k];
            }
        }
    }
}

// ---------------------------------------------------------------------------
extern "C" void kernel_launch(void* const* d_in, const int* in_sizes, int n_in,
                              void* d_out, int out_size) {
    const int*   node_c     = (const int*)d_in[0];
    const int*   cond_c     = (const int*)d_in[1];
    const float* cond_feats = (const float*)d_in[2];
    const float* t          = (const float*)d_in[3];
    const float* W_proj     = (const float*)d_in[4];
    const float* b_proj     = (const float*)d_in[5];
    const float* W_l1       = (const float*)d_in[6];
    const float* b_l1       = (const float*)d_in[7];
    const float* W_l2       = (const float*)d_in[8];
    const float* b_l2       = (const float*)d_in[9];
    const float* W_t1       = (const float*)d_in[10];
    const float* b_t1       = (const float*)d_in[11];
    const float* W_t2       = (const float*)d_in[12];
    const float* b_t2       = (const float*)d_in[13];
    float* out = (float*)d_out;

    const int mlp_smem = (32 * 256 + 256 * 33) * (int)sizeof(float);  // 66560 B
    cudaFuncSetAttribute(k_mlp, cudaFuncAttributeMaxDynamicSharedMemorySize, mlp_smem);

    k_tfeats<<<1, 256>>>(t, W_t1, b_t1, W_t2, b_t2);

    dim3 gknn(NN / 128, GG);
    k_knn<<<gknn, 128>>>(node_c, cond_c);

    k_merge<<<NN / 8, 256>>>(cond_feats);

    k_mlp<<<NN / 32, 256, mlp_smem>>>(W_proj, b_proj, W_l1, b_l1, W_l2, b_l2, out);

    (void)in_sizes; (void)n_in; (void)out_size;
}

// round 3
// speedup vs baseline: 1.3751x; 1.3751x over previous
#include <cuda_runtime.h>
#include <cfloat>
#include <math.h>

// Problem constants
#define NN 16384
#define MM 32768
#define KK 8
#define CC 256
#define GG 4                  // M-splits for KNN parallelism
#define MSEG (MM / GG)        // 8192
#define TILE 1024             // cond candidates per shared tile

// Scratch (device globals; no allocations allowed)
__device__ float g_pd[GG * NN * KK];   // partial top-8 squared dists
__device__ int   g_pi[GG * NN * KK];   // partial top-8 indices
__device__ float g_favg[NN * CC];      // weighted-average features
__device__ float g_h1[NN * CC];        // MLP intermediate 1 (matches)
__device__ float g_h2[NN * CC];        // MLP intermediate 2 (leaky l1)
__device__ float g_tf[CC];             // timestep feature vector

// ---------------------------------------------------------------------------
// Kernel 1: timestep embedding -> 2-layer MLP -> g_tf[256]
// ---------------------------------------------------------------------------
__global__ void k_tfeats(const float* __restrict__ t,
                         const float* __restrict__ Wt1, const float* __restrict__ bt1,
                         const float* __restrict__ Wt2, const float* __restrict__ bt2) {
    __shared__ float emb[96];
    __shared__ float h1[96];
    int tid = threadIdx.x;
    float tv = t[0];
    if (tid < 48) {
        const double c64 = -9.210340371976184 / 47.0;
        float cf = (float)c64;
        float arg = __fmul_rn((float)tid, cf);
        float f = (float)exp((double)arg);
        float e = __fmul_rn(tv, f);
        emb[tid]      = (float)sin((double)e);
        emb[tid + 48] = (float)cos((double)e);
    }
    __syncthreads();
    if (tid < 96) {
        float acc = 0.0f;
        #pragma unroll 8
        for (int j = 0; j < 96; ++j) acc += emb[j] * Wt1[tid * 96 + j];
        acc += bt1[tid];
        h1[tid] = (acc >= 0.0f) ? acc : 0.1f * acc;
    }
    __syncthreads();
    if (tid < 256) {
        float acc = 0.0f;
        #pragma unroll 8
        for (int j = 0; j < 96; ++j) acc += h1[j] * Wt2[tid * 96 + j];
        acc += bt2[tid];
        g_tf[tid] = acc;
    }
}

// ---------------------------------------------------------------------------
// Kernel 2: brute-force KNN (exact XLA fmla-chain fp scheme; do not touch)
// ---------------------------------------------------------------------------
__global__ void __launch_bounds__(128) k_knn(const int* __restrict__ node_c,
                                             const int* __restrict__ cond_c) {
    __shared__ float4 sc[TILE];
    int n = blockIdx.x * 128 + threadIdx.x;

    const int4 nc = ((const int4*)node_c)[n];
    float nx = __fmul_rn(__fadd_rn((float)nc.y, 8.0f), 0.05f);
    float ny = __fmul_rn(__fadd_rn((float)nc.z, 8.0f), 0.05f);
    float nz = __fmul_rn(__fadd_rn((float)nc.w, 8.0f), 0.05f);

    float bd[KK];
    int   bi[KK];
    #pragma unroll
    for (int s = 0; s < KK; ++s) { bd[s] = FLT_MAX; bi[s] = 0x7fffffff; }

    const int m0 = blockIdx.y * MSEG;

    for (int t0 = 0; t0 < MSEG; t0 += TILE) {
        for (int j = threadIdx.x; j < TILE; j += 128) {
            int4 cc = ((const int4*)cond_c)[m0 + t0 + j];
            sc[j] = make_float4(__fmul_rn(__fadd_rn((float)cc.y, 0.5f), 0.01f),
                                __fmul_rn(__fadd_rn((float)cc.z, 0.5f), 0.01f),
                                __fmul_rn(__fadd_rn((float)cc.w, 0.5f), 0.01f),
                                0.0f);
        }
        __syncthreads();

        #pragma unroll 4
        for (int j = 0; j < TILE; ++j) {
            float4 p = sc[j];
            float dx = __fadd_rn(nx, -p.x);
            float dy = __fadd_rn(ny, -p.y);
            float dz = __fadd_rn(nz, -p.z);
            float d = __fmaf_rn(dz, dz, __fmaf_rn(dy, dy, __fmul_rn(dx, dx)));
            if (d < bd[KK - 1]) {
                bd[KK - 1] = d;
                bi[KK - 1] = m0 + t0 + j;
                #pragma unroll
                for (int s = KK - 1; s > 0; --s) {
                    if (bd[s] < bd[s - 1]) {
                        float td = bd[s]; bd[s] = bd[s - 1]; bd[s - 1] = td;
                        int   ti = bi[s]; bi[s] = bi[s - 1]; bi[s - 1] = ti;
                    }
                }
            }
        }
        __syncthreads();
    }

    int base = (blockIdx.y * NN + n) * KK;
    #pragma unroll
    for (int s = 0; s < KK; ++s) {
        g_pd[base + s] = bd[s];
        g_pi[base + s] = bi[s];
    }
}

// ---------------------------------------------------------------------------
// Kernel 3: merge partials -> top-8, weights, weighted feature gather
// ---------------------------------------------------------------------------
__global__ void __launch_bounds__(256) k_merge(const float* __restrict__ cond_feats) {
    int warp = threadIdx.x >> 5;
    int lane = threadIdx.x & 31;
    int n = blockIdx.x * 8 + warp;

    int src = (((lane >> 3) * NN + n) * KK) + (lane & 7);
    float d  = g_pd[src];
    int   id = g_pi[src];

    float wd[KK];
    int   wi[KK];
    #pragma unroll
    for (int k = 0; k < KK; ++k) {
        float bdv = d; int biv = id;
        #pragma unroll
        for (int off = 16; off > 0; off >>= 1) {
            float od = __shfl_xor_sync(0xffffffffu, bdv, off);
            int   oi = __shfl_xor_sync(0xffffffffu, biv, off);
            if (od < bdv || (od == bdv && oi < biv)) { bdv = od; biv = oi; }
        }
        wd[k] = bdv; wi[k] = biv;
        if (id == biv) d = FLT_MAX;
    }

    float w[KK];
    float wsum = 0.0f;
    #pragma unroll
    for (int k = 0; k < KK; ++k) {
        float dist = fmaxf(sqrtf(wd[k]), 1e-6f);
        w[k] = 1.0f / dist;
        wsum += w[k];
    }
    #pragma unroll
    for (int k = 0; k < KK; ++k) w[k] = w[k] / wsum;

    const float* rp[KK];
    #pragma unroll
    for (int k = 0; k < KK; ++k) rp[k] = cond_feats + (size_t)wi[k] * CC;

    float* outp = g_favg + (size_t)n * CC;
    #pragma unroll
    for (int j = 0; j < 8; ++j) {
        int c = lane + j * 32;
        float acc = 0.0f;
        #pragma unroll
        for (int k = 0; k < KK; ++k) acc = fmaf(w[k], rp[k][c], acc);
        outp[c] = acc;
    }
}

// ---------------------------------------------------------------------------
// Kernel 4: register-blocked SGEMM  Y[16384,256] = X @ W^T (+bias, act, tf)
// 128x128 tile, 256 threads, 8x8 micro-tile, double-buffered smem,
// software-pipelined global loads. K=256 in 8-wide chunks (32 k-tiles).
// ACT=1: leaky_relu(0.1) epilogue. ADDTF=1: add g_tf broadcast.
// ---------------------------------------------------------------------------
#define SP 132   // smem pitch (floats), padded: breaks transpose-store conflicts
template<int ACT, int ADDTF>
__global__ void __launch_bounds__(256, 2) k_gemm(const float* __restrict__ X,
                                                 const float* __restrict__ W,
                                                 const float* __restrict__ bias,
                                                 float* __restrict__ Y) {
    __shared__ float As[2][8][SP];
    __shared__ float Bs[2][8][SP];

    const int t   = threadIdx.x;
    const int tx  = t & 15;          // 0..15 : col group
    const int ty  = t >> 4;          // 0..15 : row group
    const int row0 = blockIdx.x * 128;
    const int col0 = blockIdx.y * 128;

    // global load mapping: thread t loads one float4 of A and one of B per k-tile
    const int lrow = t >> 1;          // 0..127
    const int lk4  = (t & 1) * 4;     // 0 or 4
    const float* Ag = X + (size_t)(row0 + lrow) * CC + lk4;
    const float* Bg = W + (size_t)(col0 + lrow) * CC + lk4;

    float4 afrag = *(const float4*)Ag;
    float4 bfrag = *(const float4*)Bg;

    // store k-tile 0 (transposed) into buffer 0
    As[0][lk4 + 0][lrow] = afrag.x;
    As[0][lk4 + 1][lrow] = afrag.y;
    As[0][lk4 + 2][lrow] = afrag.z;
    As[0][lk4 + 3][lrow] = afrag.w;
    Bs[0][lk4 + 0][lrow] = bfrag.x;
    Bs[0][lk4 + 1][lrow] = bfrag.y;
    Bs[0][lk4 + 2][lrow] = bfrag.z;
    Bs[0][lk4 + 3][lrow] = bfrag.w;
    __syncthreads();

    float acc[8][8];
    #pragma unroll
    for (int i = 0; i < 8; ++i)
        #pragma unroll
        for (int j = 0; j < 8; ++j) acc[i][j] = 0.0f;

    #pragma unroll 1
    for (int kt = 0; kt < 32; ++kt) {
        int buf = kt & 1;
        if (kt < 31) {
            afrag = *(const float4*)(Ag + (kt + 1) * 8);
            bfrag = *(const float4*)(Bg + (kt + 1) * 8);
        }

        #pragma unroll
        for (int kk = 0; kk < 8; ++kk) {
            float4 a0 = *(const float4*)&As[buf][kk][ty * 8];
            float4 a1 = *(const float4*)&As[buf][kk][ty * 8 + 4];
            float4 b0 = *(const float4*)&Bs[buf][kk][tx * 8];
            float4 b1 = *(const float4*)&Bs[buf][kk][tx * 8 + 4];
            float av[8] = {a0.x, a0.y, a0.z, a0.w, a1.x, a1.y, a1.z, a1.w};
            float bv[8] = {b0.x, b0.y, b0.z, b0.w, b1.x, b1.y, b1.z, b1.w};
            #pragma unroll
            for (int i = 0; i < 8; ++i)
                #pragma unroll
                for (int j = 0; j < 8; ++j)
                    acc[i][j] = fmaf(av[i], bv[j], acc[i][j]);
        }

        if (kt < 31) {
            int nb = buf ^ 1;
            As[nb][lk4 + 0][lrow] = afrag.x;
            As[nb][lk4 + 1][lrow] = afrag.y;
            As[nb][lk4 + 2][lrow] = afrag.z;
            As[nb][lk4 + 3][lrow] = afrag.w;
            Bs[nb][lk4 + 0][lrow] = bfrag.x;
            Bs[nb][lk4 + 1][lrow] = bfrag.y;
            Bs[nb][lk4 + 2][lrow] = bfrag.z;
            Bs[nb][lk4 + 3][lrow] = bfrag.w;
            __syncthreads();
        }
    }

    // epilogue
    float bb[8], tf[8];
    #pragma unroll
    for (int j = 0; j < 8; ++j) {
        int c = col0 + tx * 8 + j;
        bb[j] = bias[c];
        if (ADDTF) tf[j] = g_tf[c];
    }

    #pragma unroll
    for (int i = 0; i < 8; ++i) {
        int r = row0 + ty * 8 + i;
        float o[8];
        #pragma unroll
        for (int j = 0; j < 8; ++j) {
            float v = acc[i][j] + bb[j];
            if (ACT)   v = (v >= 0.0f) ? v : 0.1f * v;
            if (ADDTF) v = v + tf[j];
            o[j] = v;
        }
        float4* yp = (float4*)(Y + (size_t)r * CC + col0 + tx * 8);
        yp[0] = make_float4(o[0], o[1], o[2], o[3]);
        yp[1] = make_float4(o[4], o[5], o[6], o[7]);
    }
}

// ---------------------------------------------------------------------------
extern "C" void kernel_launch(void* const* d_in, const int* in_sizes, int n_in,
                              void* d_out, int out_size) {
    const int*   node_c     = (const int*)d_in[0];
    const int*   cond_c     = (const int*)d_in[1];
    const float* cond_feats = (const float*)d_in[2];
    const float* t          = (const float*)d_in[3];
    const float* W_proj     = (const float*)d_in[4];
    const float* b_proj     = (const float*)d_in[5];
    const float* W_l1       = (const float*)d_in[6];
    const float* b_l1       = (const float*)d_in[7];
    const float* W_l2       = (const float*)d_in[8];
    const float* b_l2       = (const float*)d_in[9];
    const float* W_t1       = (const float*)d_in[10];
    const float* b_t1       = (const float*)d_in[11];
    const float* W_t2       = (const float*)d_in[12];
    const float* b_t2       = (const float*)d_in[13];
    float* out = (float*)d_out;

    float* h1; cudaGetSymbolAddress((void**)&h1, g_h1);
    float* h2; cudaGetSymbolAddress((void**)&h2, g_h2);
    float* fa; cudaGetSymbolAddress((void**)&fa, g_favg);

    k_tfeats<<<1, 256>>>(t, W_t1, b_t1, W_t2, b_t2);

    dim3 gknn(NN / 128, GG);
    k_knn<<<gknn, 128>>>(node_c, cond_c);

    k_merge<<<NN / 8, 256>>>(cond_feats);

    dim3 gg(NN / 128, CC / 128);   // 128 x 2 blocks
    k_gemm<0, 0><<<gg, 256>>>(fa, W_proj, b_proj, h1);   // matches
    k_gemm<1, 0><<<gg, 256>>>(h1, W_l1, b_l1, h2);       // leaky(l1)
    k_gemm<0, 1><<<gg, 256>>>(h2, W_l2, b_l2, out);      // l2 + tf

    (void)in_sizes; (void)n_in; (void)out_size;
}